// round 12
// baseline (speedup 1.0000x reference)
#include <cuda_runtime.h>

// image [8,512,512,32] f32, slic [8,512,512,1] i32 in [1,256]
// out [8,256,32] f32 = segment_sum(image) / segment_count_nonzero(image) per channel.
//
// Bin-then-gather v4.
//   scatter: per-block SMEM cursors (R11, measured ~18us). No global atomics,
//            counts overwritten wholesale each call (no scratch zeroing).
//   gather : NO stitching (R11's serial 128-wide prefix scan + 4096-slot
//            stage cost ~35us of prologue). Each warp walks its cells
//            directly: cell offset line (CAP=32 ints = one 128B line) into
//            registers, then per 4-pixel group 1 SHFL + 1 LDG.128 (512B).

#define BATCH 8
#define HW    (512*512)
#define C     32
#define S     256
#define SBLK  128                 // scatter blocks per image
#define SPIX  (HW / SBLK)         // 2048 pixels per scatter block
#define CAP   32                  // per-cell capacity: Poisson(8), P(>32)~1e-11
#define NCELL (BATCH * SBLK * S)  // 262144

__device__ int g_cnt [NCELL];         // 1MB   (overwritten every call)
__device__ int g_bins[NCELL * CAP];   // 33.5MB: pixel byte-offsets within image

// ---------------------------------------------------------------------------
// Kernel 1: scatter. 1024 blocks x 256 threads, 8 pixels/thread (2x int4).
// ---------------------------------------------------------------------------
__global__ void __launch_bounds__(256)
scatter(const int* __restrict__ slic) {
    __shared__ int cur[S];

    const int b   = blockIdx.x >> 7;          // image
    const int blk = blockIdx.x & (SBLK - 1);  // block within image

    cur[threadIdx.x] = 0;                     // blockDim == S == 256
    __syncthreads();

    const int pbase = blk * SPIX;
    const int4* __restrict__ sl =
        (const int4*)(slic + (size_t)b * HW + pbase);
    const int cellb = (b * SBLK + blk) * S;

    #pragma unroll
    for (int j = 0; j < 2; j++) {
        const int4 s4 = sl[j * 256 + threadIdx.x];            // coalesced
        const int  p  = pbase + j * 1024 + threadIdx.x * 4;   // pixel in image
        int s, slot;
        s = s4.x - 1; slot = atomicAdd(&cur[s], 1); if (slot < CAP) g_bins[(cellb + s) * CAP + slot] = (p    ) << 7;
        s = s4.y - 1; slot = atomicAdd(&cur[s], 1); if (slot < CAP) g_bins[(cellb + s) * CAP + slot] = (p + 1) << 7;
        s = s4.z - 1; slot = atomicAdd(&cur[s], 1); if (slot < CAP) g_bins[(cellb + s) * CAP + slot] = (p + 2) << 7;
        s = s4.w - 1; slot = atomicAdd(&cur[s], 1); if (slot < CAP) g_bins[(cellb + s) * CAP + slot] = (p + 3) << 7;
    }
    __syncthreads();

    const int c = cur[threadIdx.x];
    g_cnt[cellb + threadIdx.x] = c < CAP ? c : CAP;           // coalesced
}

// ---------------------------------------------------------------------------
// Kernel 2: gather + finalize. One block (8 warps) per (image, segment).
//   Warp w walks cells r = w, w+8, ..., w+120 (16 cells, mean 8 pixels each).
//   Per cell: one coalesced 128B offset-line load (lane = slot), then per
//   4-pixel group one SHFL (per-lane src 4g+q) + one LDG.128 of 512B
//   (lane q=l>>5? -> q=l>>3 owns pixel 4g+q, sub=l&7 owns channel quad).
//   Register float4 accumulator + int4 nonzero count; denominator IS
//   count_nonzero. shfl-xor reduce over pixel-slot groups, cross-warp via
//   smem, divide, float4 store. No atomics, ~2.5KB smem, trivial prologue.
// ---------------------------------------------------------------------------
__global__ void __launch_bounds__(256, 6)
gather(const float* __restrict__ img, float* __restrict__ out) {
    __shared__ float4 s_acc[8 * 8];
    __shared__ int4   s_nc [8 * 8];

    const int bin  = blockIdx.x;           // b*256 + s
    const int b    = bin >> 8;
    const int s    = bin & 255;
    const int warp = threadIdx.x >> 5;
    const int lane = threadIdx.x & 31;
    const int q    = lane >> 3;            // pixel slot within a group
    const int sub  = lane & 7;             // channel quad

    const char* __restrict__ base =
        (const char*)(img + (size_t)b * HW * C) + sub * 16;

    float4 acc = make_float4(0.f, 0.f, 0.f, 0.f);
    int4   nc  = make_int4(0, 0, 0, 0);

    for (int r = warp; r < SBLK; r += 8) {
        const int cell = (b * SBLK + r) * S + s;
        const int cnt  = g_cnt[cell];                        // broadcast load
        const int idx  = g_bins[cell * CAP + lane];          // one 128B line
        const int ng   = (cnt + 3) >> 2;

        for (int g = 0; g < ng; g++) {
            const int pi  = 4 * g + q;
            const int off = __shfl_sync(0xffffffffu, idx, pi);
            if (pi < cnt) {
                const float4 v = *(const float4*)(base + off);   // 512B/warp
                acc.x += v.x; acc.y += v.y; acc.z += v.z; acc.w += v.w;
                nc.x += (v.x != 0.0f); nc.y += (v.y != 0.0f);
                nc.z += (v.z != 0.0f); nc.w += (v.w != 0.0f);
            }
        }
    }

    // Reduce across the 4 pixel-slot groups (lanes l, l^8, l^16, l^24).
    #pragma unroll
    for (int d = 8; d < 32; d <<= 1) {
        acc.x += __shfl_xor_sync(0xffffffffu, acc.x, d);
        acc.y += __shfl_xor_sync(0xffffffffu, acc.y, d);
        acc.z += __shfl_xor_sync(0xffffffffu, acc.z, d);
        acc.w += __shfl_xor_sync(0xffffffffu, acc.w, d);
        nc.x  += __shfl_xor_sync(0xffffffffu, nc.x,  d);
        nc.y  += __shfl_xor_sync(0xffffffffu, nc.y,  d);
        nc.z  += __shfl_xor_sync(0xffffffffu, nc.z,  d);
        nc.w  += __shfl_xor_sync(0xffffffffu, nc.w,  d);
    }
    if (lane < 8) { s_acc[warp * 8 + lane] = acc; s_nc[warp * 8 + lane] = nc; }
    __syncthreads();

    if (warp == 0 && lane < 8) {
        float4 t = make_float4(0.f, 0.f, 0.f, 0.f);
        int4   z = make_int4(0, 0, 0, 0);
        #pragma unroll
        for (int w = 0; w < 8; w++) {
            const float4 a = s_acc[w * 8 + lane];
            const int4   m = s_nc [w * 8 + lane];
            t.x += a.x; t.y += a.y; t.z += a.z; t.w += a.w;
            z.x += m.x; z.y += m.y; z.z += m.z; z.w += m.w;
        }
        float4 o;
        o.x = t.x / (float)z.x;  o.y = t.y / (float)z.y;
        o.z = t.z / (float)z.z;  o.w = t.w / (float)z.w;
        ((float4*)out)[bin * 8 + lane] = o;   // out[b][s][lane*4 .. +4)
    }
}

// ---------------------------------------------------------------------------
// Entry point (graph-capturable: two kernel launches, no sync, no alloc).
// ---------------------------------------------------------------------------
extern "C" void kernel_launch(void* const* d_in, const int* in_sizes, int n_in,
                              void* d_out, int out_size) {
    const float* img  = (const float*)d_in[0];   // image, 67108864 f32
    const int*   slic = (const int*)  d_in[1];   // slic,   2097152 i32
    float*       out  = (float*)d_out;           // 65536 f32

    (void)in_sizes; (void)n_in; (void)out_size;

    scatter<<<BATCH * SBLK, 256>>>(slic);        // 1024 blocks
    gather<<<BATCH * S, 256>>>(img, out);        // one block per (image,segment)
}

// round 13
// speedup vs baseline: 1.1776x; 1.1776x over previous
#include <cuda_runtime.h>

// image [8,512,512,32] f32, slic [8,512,512,1] i32 in [1,256]
// out [8,256,32] f32 = segment_sum(image) / segment_count_nonzero(image) per channel.
//
// Bin-then-gather v5.
//   scatter: per-block SMEM cursors (measured ~18us since R11). No global
//            atomics; counts overwritten wholesale (no scratch zeroing).
//   gather : flat smem-staged list (R8's winning shape), but with
//            - PARALLEL Hillis-Steele scan of the 128 cell counts
//              (R11 failed on a serial thread-0 scan, ~2.5K-cyc chain),
//            - float4-lane hot loop: 1 LDS + 1 LDG.128 (512B) per 4 pixels,
//            - manual 4-way load batching for guaranteed MLP=4/warp
//              (R12 failed on per-cell dependency chains, DRAM 34%).

#define BATCH 8
#define HW    (512*512)
#define C     32
#define S     256
#define SBLK  128                 // scatter blocks per image
#define SPIX  (HW / SBLK)         // 2048 pixels per scatter block
#define CAP   32                  // per-cell capacity: Poisson(8), P(>32)~1e-11
#define NCELL (BATCH * SBLK * S)  // 262144

__device__ int g_cnt [NCELL];         // 1MB   (overwritten every call)
__device__ int g_bins[NCELL * CAP];   // 33.5MB: pixel byte-offsets within image

// ---------------------------------------------------------------------------
// Kernel 1: scatter. 1024 blocks x 256 threads, 8 pixels/thread (2x int4).
// ---------------------------------------------------------------------------
__global__ void __launch_bounds__(256)
scatter(const int* __restrict__ slic) {
    __shared__ int cur[S];

    const int b   = blockIdx.x >> 7;          // image
    const int blk = blockIdx.x & (SBLK - 1);  // block within image

    cur[threadIdx.x] = 0;                     // blockDim == S == 256
    __syncthreads();

    const int pbase = blk * SPIX;
    const int4* __restrict__ sl =
        (const int4*)(slic + (size_t)b * HW + pbase);
    const int cellb = (b * SBLK + blk) * S;

    #pragma unroll
    for (int j = 0; j < 2; j++) {
        const int4 s4 = sl[j * 256 + threadIdx.x];            // coalesced
        const int  p  = pbase + j * 1024 + threadIdx.x * 4;   // pixel in image
        int s, slot;
        s = s4.x - 1; slot = atomicAdd(&cur[s], 1); if (slot < CAP) g_bins[(cellb + s) * CAP + slot] = (p    ) << 7;
        s = s4.y - 1; slot = atomicAdd(&cur[s], 1); if (slot < CAP) g_bins[(cellb + s) * CAP + slot] = (p + 1) << 7;
        s = s4.z - 1; slot = atomicAdd(&cur[s], 1); if (slot < CAP) g_bins[(cellb + s) * CAP + slot] = (p + 2) << 7;
        s = s4.w - 1; slot = atomicAdd(&cur[s], 1); if (slot < CAP) g_bins[(cellb + s) * CAP + slot] = (p + 3) << 7;
    }
    __syncthreads();

    const int c = cur[threadIdx.x];
    g_cnt[cellb + threadIdx.x] = c < CAP ? c : CAP;           // coalesced
}

// ---------------------------------------------------------------------------
// Kernel 2: gather + finalize. One block (8 warps) per (image, segment).
// ---------------------------------------------------------------------------
__global__ void __launch_bounds__(256)
gather(const float* __restrict__ img, float* __restrict__ out) {
    __shared__ int    s_idx[SBLK * CAP];   // 16KB flat byte-offset list
    __shared__ int    s_cnt[SBLK];
    __shared__ int    s_scan[SBLK];        // inclusive scan of counts
    __shared__ float4 s_acc[8 * 8];
    __shared__ int4   s_nc [8 * 8];

    const int bin  = blockIdx.x;           // b*256 + s
    const int b    = bin >> 8;
    const int s    = bin & 255;
    const int t    = threadIdx.x;
    const int warp = t >> 5;
    const int lane = t & 31;
    const int q    = lane >> 3;            // pixel slot within a group of 4
    const int sub  = lane & 7;             // channel quad

    // --- counts + PARALLEL scan (7 Hillis-Steele steps) ---
    if (t < SBLK) {
        const int c = g_cnt[(b * SBLK + t) * S + s];
        s_cnt[t]  = c;
        s_scan[t] = c;
    }
    #pragma unroll
    for (int d = 1; d < SBLK; d <<= 1) {
        __syncthreads();
        int v = 0;
        if (t < SBLK && t >= d) v = s_scan[t - d];
        __syncthreads();
        if (t < SBLK && t >= d) s_scan[t] += v;
    }
    __syncthreads();

    // --- stage: compact valid slots into the flat list (16 rounds) ---
    for (int j = t; j < SBLK * CAP; j += 256) {
        const int r = j >> 5, i = j & (CAP - 1);
        const int c = s_cnt[r];
        if (i < c) {
            const int off = (r ? s_scan[r - 1] : 0);
            s_idx[off + i] = g_bins[((b * SBLK + r) * S + s) * CAP + i];
        }
    }
    __syncthreads();

    const int n  = s_scan[SBLK - 1];       // pixels in this segment
    const int ng = (n + 3) >> 2;           // 4-pixel groups

    const char* __restrict__ base =
        (const char*)(img + (size_t)b * HW * C) + sub * 16;

    float4 acc = make_float4(0.f, 0.f, 0.f, 0.f);
    int4   nc  = make_int4(0, 0, 0, 0);

    // --- hot loop: batches of 4 groups -> 4 independent LDS then 4
    //     independent LDG.128 (512B each) in flight per warp ---
    for (int g0 = warp; g0 < ng; g0 += 32) {
        int off[4];
        #pragma unroll
        for (int u = 0; u < 4; u++) {
            const int g  = g0 + u * 8;
            const int pi = 4 * g + q;
            off[u] = (g < ng && pi < n) ? s_idx[pi] : -1;
        }
        #pragma unroll
        for (int u = 0; u < 4; u++) {
            if (off[u] >= 0) {
                const float4 v = *(const float4*)(base + off[u]);
                acc.x += v.x; acc.y += v.y; acc.z += v.z; acc.w += v.w;
                nc.x += (v.x != 0.0f); nc.y += (v.y != 0.0f);
                nc.z += (v.z != 0.0f); nc.w += (v.w != 0.0f);
            }
        }
    }

    // --- reduce across pixel-slot groups (lanes l, l^8, l^16, l^24) ---
    #pragma unroll
    for (int d = 8; d < 32; d <<= 1) {
        acc.x += __shfl_xor_sync(0xffffffffu, acc.x, d);
        acc.y += __shfl_xor_sync(0xffffffffu, acc.y, d);
        acc.z += __shfl_xor_sync(0xffffffffu, acc.z, d);
        acc.w += __shfl_xor_sync(0xffffffffu, acc.w, d);
        nc.x  += __shfl_xor_sync(0xffffffffu, nc.x,  d);
        nc.y  += __shfl_xor_sync(0xffffffffu, nc.y,  d);
        nc.z  += __shfl_xor_sync(0xffffffffu, nc.z,  d);
        nc.w  += __shfl_xor_sync(0xffffffffu, nc.w,  d);
    }
    if (lane < 8) { s_acc[warp * 8 + lane] = acc; s_nc[warp * 8 + lane] = nc; }
    __syncthreads();

    if (warp == 0 && lane < 8) {
        float4 tt = make_float4(0.f, 0.f, 0.f, 0.f);
        int4   z  = make_int4(0, 0, 0, 0);
        #pragma unroll
        for (int w = 0; w < 8; w++) {
            const float4 a = s_acc[w * 8 + lane];
            const int4   m = s_nc [w * 8 + lane];
            tt.x += a.x; tt.y += a.y; tt.z += a.z; tt.w += a.w;
            z.x  += m.x; z.y  += m.y; z.z  += m.z; z.w  += m.w;
        }
        float4 o;
        o.x = tt.x / (float)z.x;  o.y = tt.y / (float)z.y;
        o.z = tt.z / (float)z.z;  o.w = tt.w / (float)z.w;
        ((float4*)out)[bin * 8 + lane] = o;   // out[b][s][lane*4 .. +4)
    }
}

// ---------------------------------------------------------------------------
// Entry point (graph-capturable: two kernel launches, no sync, no alloc).
// ---------------------------------------------------------------------------
extern "C" void kernel_launch(void* const* d_in, const int* in_sizes, int n_in,
                              void* d_out, int out_size) {
    const float* img  = (const float*)d_in[0];   // image, 67108864 f32
    const int*   slic = (const int*)  d_in[1];   // slic,   2097152 i32
    float*       out  = (float*)d_out;           // 65536 f32

    (void)in_sizes; (void)n_in; (void)out_size;

    scatter<<<BATCH * SBLK, 256>>>(slic);        // 1024 blocks
    gather<<<BATCH * S, 256>>>(img, out);        // one block per (image,segment)
}

// round 14
// speedup vs baseline: 1.3637x; 1.1580x over previous
#include <cuda_runtime.h>

// image [8,512,512,32] f32, slic [8,512,512,1] i32 in [1,256]
// out [8,256,32] f32 = segment_sum(image) / segment_count_nonzero(image) per channel.
//
// Bin-then-gather v6.
//   scatter: per-block SMEM cursors (~18us proven). Scratch layout TRANSPOSED
//            to [b][s][blk] so gather's reads are contiguous.
//   gather : R8's winning load shape (lane = channel, ONE 128B line per LDG —
//            float4 multi-line LDGs cost ~2x in L1tex within-LDG replays and
//            collapsed DRAM to 40%), batched x8 for MLP, single-warp shfl
//            scan prologue (R13's 14-barrier scan -> ~1 barrier).

#define BATCH 8
#define HW    (512*512)
#define C     32
#define S     256
#define SBLK  128                 // scatter blocks per image
#define SPIX  (HW / SBLK)         // 2048 pixels per scatter block
#define CAP   32                  // per-cell capacity: Poisson(8), P(>32)~1e-11
#define NCELL (BATCH * S * SBLK)  // 262144

// Transposed: cell (b,s,blk) = (b*S + s)*SBLK + blk.
__device__ int g_cnt [NCELL];         // 1MB   (overwritten every call)
__device__ int g_bins[NCELL * CAP];   // 33.5MB: pixel byte-offsets within image

// ---------------------------------------------------------------------------
// Kernel 1: scatter. 1024 blocks x 256 threads, 8 pixels/thread (2x int4).
//   SMEM cursors, no global atomics. Counts/bins written scattered (stride
//   SBLK) — that cost hides behind the slic stream; gather reads contiguous.
// ---------------------------------------------------------------------------
__global__ void __launch_bounds__(256)
scatter(const int* __restrict__ slic) {
    __shared__ int cur[S];

    const int b   = blockIdx.x >> 7;          // image
    const int blk = blockIdx.x & (SBLK - 1);  // block within image

    cur[threadIdx.x] = 0;                     // blockDim == S == 256
    __syncthreads();

    const int pbase = blk * SPIX;
    const int4* __restrict__ sl =
        (const int4*)(slic + (size_t)b * HW + pbase);

    #pragma unroll
    for (int j = 0; j < 2; j++) {
        const int4 s4 = sl[j * 256 + threadIdx.x];            // coalesced
        const int  p  = pbase + j * 1024 + threadIdx.x * 4;   // pixel in image
        int s, slot;
        s = s4.x - 1; slot = atomicAdd(&cur[s], 1); if (slot < CAP) g_bins[(((b * S + s) * SBLK) + blk) * CAP + slot] = (p    ) << 7;
        s = s4.y - 1; slot = atomicAdd(&cur[s], 1); if (slot < CAP) g_bins[(((b * S + s) * SBLK) + blk) * CAP + slot] = (p + 1) << 7;
        s = s4.z - 1; slot = atomicAdd(&cur[s], 1); if (slot < CAP) g_bins[(((b * S + s) * SBLK) + blk) * CAP + slot] = (p + 2) << 7;
        s = s4.w - 1; slot = atomicAdd(&cur[s], 1); if (slot < CAP) g_bins[(((b * S + s) * SBLK) + blk) * CAP + slot] = (p + 3) << 7;
    }
    __syncthreads();

    const int c = cur[threadIdx.x];
    g_cnt[(b * S + threadIdx.x) * SBLK + blk] = c < CAP ? c : CAP;
}

// ---------------------------------------------------------------------------
// Kernel 2: gather + finalize. One block (8 warps) per (image, segment).
//   Prologue: warp 0 loads the 128 cell counts (one coalesced int4/lane),
//   does an in-register + shfl exclusive scan, publishes offsets. ONE block
//   barrier. Staging reads are fully contiguous (bin*4096 + j).
//   Hot loop: pixel i -> LDS broadcast of byte offset, LDG.32 with
//   lane = channel (exactly one 128B line per warp-instruction), batched
//   x8 for 8 loads in flight per warp. Register accumulate; denominator
//   is count_nonzero directly. No atomics.
// ---------------------------------------------------------------------------
__global__ void __launch_bounds__(256)
gather(const float* __restrict__ img, float* __restrict__ out) {
    __shared__ int   s_idx[SBLK * CAP];   // 16KB flat byte-offset list
    __shared__ int   s_cnt[SBLK];
    __shared__ int   s_off[SBLK];         // exclusive offsets
    __shared__ int   s_n;
    __shared__ float s_acc[8 * 32];
    __shared__ int   s_nz [8 * 32];

    const int bin  = blockIdx.x;          // b*256 + s
    const int b    = bin >> 8;
    const int t    = threadIdx.x;
    const int warp = t >> 5;
    const int lane = t & 31;

    // --- warp-0 scan of the 128 counts ---
    if (warp == 0) {
        const int4 c4 = ((const int4*)g_cnt)[bin * (SBLK / 4) + lane];  // coalesced
        const int sum = c4.x + c4.y + c4.z + c4.w;
        // exclusive scan of per-lane sums via shfl
        int run = sum;
        #pragma unroll
        for (int d = 1; d < 32; d <<= 1) {
            const int v = __shfl_up_sync(0xffffffffu, run, d);
            if (lane >= d) run += v;
        }
        const int excl = run - sum;                 // exclusive prefix for lane
        s_cnt[lane * 4 + 0] = c4.x;  s_off[lane * 4 + 0] = excl;
        s_cnt[lane * 4 + 1] = c4.y;  s_off[lane * 4 + 1] = excl + c4.x;
        s_cnt[lane * 4 + 2] = c4.z;  s_off[lane * 4 + 2] = excl + c4.x + c4.y;
        s_cnt[lane * 4 + 3] = c4.w;  s_off[lane * 4 + 3] = excl + c4.x + c4.y + c4.z;
        if (lane == 31) s_n = run;
    }
    __syncthreads();

    // --- stage: contiguous 16KB read, compact into flat list ---
    const int binbase = bin * (SBLK * CAP);
    for (int j = t; j < SBLK * CAP; j += 256) {
        const int r = j >> 5, i = j & (CAP - 1);
        if (i < s_cnt[r]) s_idx[s_off[r] + i] = g_bins[binbase + j];
    }
    __syncthreads();

    const int n = s_n;
    const float* __restrict__ base = img + (size_t)b * HW * C + lane;

    float acc = 0.0f;
    int   nz  = 0;

    // --- hot loop: warp w owns i in [w*8, w*8+8) mod 64; batch 8 offsets
    //     (independent LDS) then 8 single-line LDGs in flight. ---
    for (int i0 = warp * 8; i0 < n; i0 += 64) {
        int off[8];
        #pragma unroll
        for (int u = 0; u < 8; u++) {
            const int i = i0 + u;
            off[u] = (i < n) ? s_idx[i] : -1;
        }
        #pragma unroll
        for (int u = 0; u < 8; u++) {
            if (off[u] >= 0) {
                const float v = *(const float*)((const char*)base + off[u]);
                acc += v;
                nz  += (v != 0.0f);                // denominator = count_nonzero
            }
        }
    }

    s_acc[warp * 32 + lane] = acc;
    s_nz [warp * 32 + lane] = nz;
    __syncthreads();

    if (warp == 0) {
        float tot = 0.0f;
        int   z   = 0;
        #pragma unroll
        for (int w = 0; w < 8; w++) {
            tot += s_acc[w * 32 + lane];
            z   += s_nz [w * 32 + lane];
        }
        out[bin * 32 + lane] = tot / (float)z;
    }
}

// ---------------------------------------------------------------------------
// Entry point (graph-capturable: two kernel launches, no sync, no alloc).
// ---------------------------------------------------------------------------
extern "C" void kernel_launch(void* const* d_in, const int* in_sizes, int n_in,
                              void* d_out, int out_size) {
    const float* img  = (const float*)d_in[0];   // image, 67108864 f32
    const int*   slic = (const int*)  d_in[1];   // slic,   2097152 i32
    float*       out  = (float*)d_out;           // 65536 f32

    (void)in_sizes; (void)n_in; (void)out_size;

    scatter<<<BATCH * SBLK, 256>>>(slic);        // 1024 blocks
    gather<<<BATCH * S, 256>>>(img, out);        // one block per (image,segment)
}

// round 15
// speedup vs baseline: 1.5175x; 1.1128x over previous
#include <cuda_runtime.h>

// image [8,512,512,32] f32, slic [8,512,512,1] i32 in [1,256]
// out [8,256,32] f32 = segment_sum(image) / segment_count_nonzero(image) per channel.
//
// Streaming + privatized smem atomics, v2 (2-pixel groups).
// Cross-round model: dur ~ 22-28us per LSU-wavefront-per-pixel.
//   R4 (4px groups): 1 img + 2.17 atomic-phases + 0.25 pix + junk = 3.4 -> 76us.
//   This kernel:     1 img + 1.50 atomic-phases + 0.25 lab + 0.12 pix = 2.9.
// 2px x 16-bank cosets collide only when s0 == s1 (mod 2) -> E[phases]=1.5
// (4px stride-4 cosets collide at P=1/4 with FULL 8-wide overlap -> 2.17,
//  and no bank permutation can fix that; 2px is the structural win).

#define BATCH 8
#define HW    (512*512)
#define C     32
#define S     256
#define CS    33                  // skew: bank = (s + 2*sub + j) mod 32
#define BPI   37                  // blocks per image; 296 blocks = 2/SM
#define THREADS 1024
#define CHUNKS  (HW / 32)         // 8192 32-pixel chunks per image
#define CSTRIDE (BPI * 32)        // 1184 chunks per grid sweep

// Scratch (zero at module load; finalize self-cleans every call).
__device__ float g_sums[BATCH * S * C];
__device__ float g_zero[BATCH * S * C];   // exact-zero corrections (rare path)
__device__ float g_pix [BATCH * S];

__global__ void __launch_bounds__(THREADS, 2)
seg_accum(const float* __restrict__ img, const int* __restrict__ slic) {
    __shared__ float s_sum[S * CS];   // 33.8KB skewed accumulator
    __shared__ float s_pix[S];

    const int b    = blockIdx.y;
    const int warp = threadIdx.x >> 5;
    const int lane = threadIdx.x & 31;
    const int q    = lane >> 4;       // which of the 2 pixels this lane serves
    const int sub  = lane & 15;       // channel pair within the pixel

    for (int i = threadIdx.x; i < S * CS; i += THREADS) s_sum[i] = 0.0f;
    if (threadIdx.x < S) s_pix[threadIdx.x] = 0.0f;
    __syncthreads();

    const float* __restrict__ imgb  = img  + (size_t)b * HW * C;
    const int*   __restrict__ slicb = slic + (size_t)b * HW;
    float* __restrict__ gzb = g_zero + (size_t)b * S * C;

    for (int c = blockIdx.x * 32 + warp; c < CHUNKS; c += CSTRIDE) {
        const int p0 = c * 32;

        // Pixel counts: ONE full-lane ATOMS per 32 pixels (0.12 slots/px,
        // was 0.25 with 4-active-lane adds). Coalesced 128B label line.
        const int myl = slicb[p0 + lane] - 1;
        atomicAdd(&s_pix[myl], 1.0f);

        #pragma unroll
        for (int g = 0; g < 8; g++) {
            // 4 labels for pixels p0+4g..+3; same addr all lanes -> 1 wf.
            const int4 lab = *(const int4*)(slicb + p0 + g * 4);
            const int  pg  = p0 + g * 4;

            #pragma unroll
            for (int h = 0; h < 2; h++) {          // two 2-pixel sub-groups
                const int p  = pg + h * 2;
                const int s0 = (h ? lab.z : lab.x) - 1;
                const int s1 = (h ? lab.w : lab.y) - 1;
                const int s  = q ? s1 : s0;

                // 256B contiguous per warp (2 lines, 2 wf).
                const float2 v =
                    *(const float2*)(imgb + (size_t)(p + q) * C + sub * 2);

                // banks (s + 2sub + j) mod 32: 16-bank coset per pixel;
                // the two pixels collide only if s0 == s1 (mod 2).
                atomicAdd(&s_sum[s * CS + sub * 2    ], v.x);
                atomicAdd(&s_sum[s * CS + sub * 2 + 1], v.y);

                // Exact count_nonzero: rare path off the LSU via ballot.
                if (__ballot_sync(0xffffffffu, (v.x == 0.0f) || (v.y == 0.0f))) {
                    if (v.x == 0.0f) atomicAdd(&gzb[s * C + sub * 2    ], 1.0f);
                    if (v.y == 0.0f) atomicAdd(&gzb[s * C + sub * 2 + 1], 1.0f);
                }
            }
        }
    }
    __syncthreads();

    // Flush block-private accumulators (de-skew). 296 x 8448 REDG lanes.
    float* __restrict__ gs = g_sums + (size_t)b * S * C;
    for (int i = threadIdx.x; i < S * C; i += THREADS)
        atomicAdd(&gs[i], s_sum[(i >> 5) * CS + (i & 31)]);
    if (threadIdx.x < S)
        atomicAdd(&g_pix[b * S + threadIdx.x], s_pix[threadIdx.x]);
}

// ---------------------------------------------------------------------------
// out = sum / (pixel_count - zero_count); self-clean scratch for next replay.
// (g_pix hazard confined to one warp: warp-wide load precedes lane-0 store.)
// ---------------------------------------------------------------------------
__global__ void finalize(float* __restrict__ out) {
    int i = blockIdx.x * blockDim.x + threadIdx.x;
    if (i < BATCH * S * C) {
        float cnt = g_pix[i >> 5] - g_zero[i];
        out[i] = g_sums[i] / cnt;
        g_sums[i] = 0.0f;
        g_zero[i] = 0.0f;
        if ((i & 31) == 0) g_pix[i >> 5] = 0.0f;
    }
}

// ---------------------------------------------------------------------------
// Entry point (graph-capturable: two kernel launches, no sync, no alloc).
// ---------------------------------------------------------------------------
extern "C" void kernel_launch(void* const* d_in, const int* in_sizes, int n_in,
                              void* d_out, int out_size) {
    const float* img  = (const float*)d_in[0];   // image, 67108864 f32
    const int*   slic = (const int*)  d_in[1];   // slic,   2097152 i32
    float*       out  = (float*)d_out;           // 65536 f32

    (void)in_sizes; (void)n_in; (void)out_size;

    dim3 grid(BPI, BATCH);
    seg_accum<<<grid, THREADS>>>(img, slic);

    finalize<<<(BATCH * S * C + 255) / 256, 256>>>(out);
}